// round 2
// baseline (speedup 1.0000x reference)
#include <cuda_runtime.h>
#include <math.h>
#include <float.h>

#define T_STEPS 32
#define B_SZ    512
#define S_SZ    64
#define F_IN    128
#define H1      256
#define H2      256
#define H3      128
#define M_ROWS  (T_STEPS * B_SZ)   // 16384

// Scratch (allocation-free rule: __device__ globals)
__device__ float g_spk0[T_STEPS * B_SZ * F_IN];   // 8 MB encoded spikes (mean over S)
__device__ float g_cur [T_STEPS * B_SZ * H1];     // 16 MB, reused per layer
__device__ float g_spk1[T_STEPS * B_SZ * H1];     // 16 MB
__device__ float g_spk2[T_STEPS * B_SZ * H2];     // 16 MB

// ---------------------------------------------------------------------------
// Latency encode + mean over S. Block = batch b, thread = feature f.
// ---------------------------------------------------------------------------
__global__ void encode_kernel(const float* __restrict__ x, float* __restrict__ out) {
    int b = blockIdx.x;
    int f = threadIdx.x;
    __shared__ float cnt[T_STEPS * F_IN];
#pragma unroll
    for (int t = 0; t < T_STEPS; ++t) cnt[t * F_IN + f] = 0.f;

    const float* xb = x + (size_t)b * S_SZ * F_IN + f;

    float vmin = FLT_MAX, vmax = -FLT_MAX;
#pragma unroll 8
    for (int s = 0; s < S_SZ; ++s) {
        float v = xb[s * F_IN];
        v = (v < 0.75f) ? 0.f : v;
        vmin = fminf(vmin, v);
        vmax = fmaxf(vmax, v);
    }
    float denom = vmax - vmin + 1e-8f;

    const float c1   = 0.0100001f;            // float(LAT_THR + EPS)
    const float tmax = 11.512935464920229f;   // log((0.01+1e-7)/1e-7)

#pragma unroll 4
    for (int s = 0; s < S_SZ; ++s) {
        float v = xb[s * F_IN];
        v = (v < 0.75f) ? 0.f : v;
        float xn = (v - vmin) / denom;
        float d  = fmaxf(xn, c1);
        float tt = logf(d / (d - 0.01f));
        tt = tt * 31.0f / tmax;
        float r = rintf(tt);
        r = fminf(fmaxf(r, 0.f), 31.f);
        int ti = (int)r;
        cnt[ti * F_IN + f] += 1.0f;
    }

#pragma unroll
    for (int t = 0; t < T_STEPS; ++t)
        out[(size_t)t * (B_SZ * F_IN) + (size_t)b * F_IN + f] =
            cnt[t * F_IN + f] * 0.015625f;
}

// ---------------------------------------------------------------------------
// C[m,n] = bias[n] + sum_k A[m,k] * W[n,k]
// A: (M x K) row-major, W: (N x K) row-major. BK=8, 256 threads,
// TM x TN outputs per thread ((BM/TM)*(BN/TN) must equal 256).
// All shapes divide evenly -> no bounds checks.
// ---------------------------------------------------------------------------
template<int BM, int BN, int TM, int TN>
__global__ __launch_bounds__(256)
void gemm_bias_kernel(const float* __restrict__ A,
                      const float* __restrict__ W,
                      const float* __restrict__ bias,
                      float* __restrict__ C,
                      int N, int K) {
    constexpr int BK = 8;
    __shared__ float As[BK][BM];
    __shared__ float Bs[BK][BN];

    const int tid = threadIdx.x;
    constexpr int NTX = BN / TN;            // threads along n
    const int tx = tid % NTX;
    const int ty = tid / NTX;
    const int m0 = blockIdx.y * BM;
    const int n0 = blockIdx.x * BN;

    float acc[TM][TN];
#pragma unroll
    for (int i = 0; i < TM; ++i)
#pragma unroll
        for (int j = 0; j < TN; ++j) acc[i][j] = 0.f;

    const float* Abase = A + (size_t)m0 * K;
    const float* Wbase = W + (size_t)n0 * K;

    for (int kt = 0; kt < K; kt += BK) {
        // load A tile: BM*BK floats, float4 granularity
#pragma unroll
        for (int i = tid * 4; i < BM * BK; i += 256 * 4) {
            int row = i / BK;
            int kq  = i % BK;               // 0 or 4
            float4 v = *(const float4*)(Abase + (size_t)row * K + kt + kq);
            As[kq + 0][row] = v.x; As[kq + 1][row] = v.y;
            As[kq + 2][row] = v.z; As[kq + 3][row] = v.w;
        }
        // load W tile: BN*BK floats
#pragma unroll
        for (int i = tid * 4; i < BN * BK; i += 256 * 4) {
            int row = i / BK;
            int kq  = i % BK;
            float4 v = *(const float4*)(Wbase + (size_t)row * K + kt + kq);
            Bs[kq + 0][row] = v.x; Bs[kq + 1][row] = v.y;
            Bs[kq + 2][row] = v.z; Bs[kq + 3][row] = v.w;
        }
        __syncthreads();

#pragma unroll
        for (int k = 0; k < BK; ++k) {
            float a_frag[TM], b_frag[TN];
#pragma unroll
            for (int i = 0; i < TM; i += 4) {
                float4 v = *(const float4*)&As[k][ty * TM + i];
                a_frag[i + 0] = v.x; a_frag[i + 1] = v.y;
                a_frag[i + 2] = v.z; a_frag[i + 3] = v.w;
            }
#pragma unroll
            for (int j = 0; j < TN; j += 4) {
                float4 v = *(const float4*)&Bs[k][tx * TN + j];
                b_frag[j + 0] = v.x; b_frag[j + 1] = v.y;
                b_frag[j + 2] = v.z; b_frag[j + 3] = v.w;
            }
#pragma unroll
            for (int i = 0; i < TM; ++i)
#pragma unroll
                for (int j = 0; j < TN; ++j)
                    acc[i][j] = fmaf(a_frag[i], b_frag[j], acc[i][j]);
        }
        __syncthreads();
    }

    // epilogue: add bias, vectorized store
    float bfr[TN];
#pragma unroll
    for (int j = 0; j < TN; j += 4) {
        float4 v = *(const float4*)(bias + n0 + tx * TN + j);
        bfr[j + 0] = v.x; bfr[j + 1] = v.y; bfr[j + 2] = v.z; bfr[j + 3] = v.w;
    }
#pragma unroll
    for (int i = 0; i < TM; ++i) {
        int row = m0 + ty * TM + i;
        float* cp = C + (size_t)row * N + n0 + tx * TN;
#pragma unroll
        for (int j = 0; j < TN; j += 4) {
            float4 o;
            o.x = acc[i][j + 0] + bfr[j + 0];
            o.y = acc[i][j + 1] + bfr[j + 1];
            o.z = acc[i][j + 2] + bfr[j + 2];
            o.w = acc[i][j + 3] + bfr[j + 3];
            *(float4*)(cp + j) = o;
        }
    }
}

// ---------------------------------------------------------------------------
// LIF scan (reset-by-subtraction), snntorch Leaky semantics.
// ---------------------------------------------------------------------------
__global__ void lif_scan_kernel(const float* __restrict__ cur,
                                float* __restrict__ spk, int n) {
    int i = blockIdx.x * blockDim.x + threadIdx.x;
    if (i >= n) return;
    float mem = 0.f;
#pragma unroll
    for (int t = 0; t < T_STEPS; ++t) {
        float c = cur[(size_t)t * n + i];
        float reset = (mem > 1.0f) ? 1.0f : 0.0f;
        mem = 0.9f * mem + c - reset;
        spk[(size_t)t * n + i] = (mem > 1.0f) ? 1.0f : 0.0f;
    }
}

// ---------------------------------------------------------------------------
extern "C" void kernel_launch(void* const* d_in, const int* in_sizes, int n_in,
                              void* d_out, int out_size) {
    const float* x  = (const float*)d_in[0];
    const float* W1 = (const float*)d_in[1];
    const float* b1 = (const float*)d_in[2];
    const float* W2 = (const float*)d_in[3];
    const float* b2 = (const float*)d_in[4];
    const float* W3 = (const float*)d_in[5];
    const float* b3 = (const float*)d_in[6];
    float* out = (float*)d_out;

    float *spk0, *cur, *spk1, *spk2;
    cudaGetSymbolAddress((void**)&spk0, g_spk0);
    cudaGetSymbolAddress((void**)&cur,  g_cur);
    cudaGetSymbolAddress((void**)&spk1, g_spk1);
    cudaGetSymbolAddress((void**)&spk2, g_spk2);

    // 1. encode
    encode_kernel<<<B_SZ, F_IN>>>(x, spk0);

    // 2. layer 1: (16384 x 128) @ (256 x 128)^T   -> 128x128 tiles, 8x8/thread
    {
        dim3 grid(H1 / 128, M_ROWS / 128);            // (2, 128)
        gemm_bias_kernel<128, 128, 8, 8><<<grid, 256>>>(spk0, W1, b1, cur, H1, F_IN);
        int n = B_SZ * H1;
        lif_scan_kernel<<<(n + 255) / 256, 256>>>(cur, spk1, n);
    }
    // 3. layer 2: (16384 x 256) @ (256 x 256)^T
    {
        dim3 grid(H2 / 128, M_ROWS / 128);            // (2, 128)
        gemm_bias_kernel<128, 128, 8, 8><<<grid, 256>>>(spk1, W2, b2, cur, H2, H1);
        int n = B_SZ * H2;
        lif_scan_kernel<<<(n + 255) / 256, 256>>>(cur, spk2, n);
    }
    // 4. layer 3: (16384 x 256) @ (128 x 256)^T -> 64x128 tiles, 4x8/thread
    {
        dim3 grid(H3 / 128, M_ROWS / 64);             // (1, 256)
        gemm_bias_kernel<64, 128, 4, 8><<<grid, 256>>>(spk2, W3, b3, cur, H3, H2);
        int n = B_SZ * H3;
        lif_scan_kernel<<<(n + 255) / 256, 256>>>(cur, out, n);
    }
}

// round 4
// speedup vs baseline: 1.9713x; 1.9713x over previous
#include <cuda_runtime.h>
#include <cuda_bf16.h>
#include <math.h>
#include <float.h>
#include <stdint.h>

#define T_STEPS 32
#define B_SZ    512
#define S_SZ    64
#define F_IN    128
#define H1      256
#define H2      256
#define H3      128
#define M_ROWS  (T_STEPS * B_SZ)   // 16384

// ---------------------------------------------------------------------------
// Scratch (__device__ globals; no allocation allowed)
// ---------------------------------------------------------------------------
__device__ __nv_bfloat16 g_spk0[M_ROWS * F_IN];
__device__ __nv_bfloat16 g_spk1[M_ROWS * H1];
__device__ __nv_bfloat16 g_spk2[M_ROWS * H2];
__device__ float         g_cur [M_ROWS * H1];
__device__ __nv_bfloat16 g_wsplit[9][H1 * H1];   // [layer*3+split][N*K]

// ---------------------------------------------------------------------------
// PTX helpers (baseline sm_80+ features only; no tcgen05)
// ---------------------------------------------------------------------------
__device__ __forceinline__ uint32_t smem_u32(const void* p) {
    uint32_t a;
    asm("{ .reg .u64 t; cvta.to.shared.u64 t, %1; cvt.u32.u64 %0, t; }" : "=r"(a) : "l"(p));
    return a;
}
#define CP_ASYNC16(dst, src) \
    asm volatile("cp.async.cg.shared.global [%0], [%1], 16;" :: "r"(dst), "l"(src))
#define CP_COMMIT() asm volatile("cp.async.commit_group;")
#define CP_WAIT(N)  asm volatile("cp.async.wait_group %0;" :: "n"(N))

#define LDSM_X4(r0, r1, r2, r3, addr)                                   \
    asm volatile("ldmatrix.sync.aligned.m8n8.x4.shared.b16 "            \
                 "{%0,%1,%2,%3}, [%4];"                                 \
                 : "=r"(r0), "=r"(r1), "=r"(r2), "=r"(r3) : "r"(addr))
#define LDSM_X2(r0, r1, addr)                                           \
    asm volatile("ldmatrix.sync.aligned.m8n8.x2.shared.b16 "            \
                 "{%0,%1}, [%2];" : "=r"(r0), "=r"(r1) : "r"(addr))

#define MMA_BF16(c, a, b0, b1)                                          \
    asm volatile("mma.sync.aligned.m16n8k16.row.col.f32.bf16.bf16.f32 " \
                 "{%0,%1,%2,%3}, {%4,%5,%6,%7}, {%8,%9}, {%0,%1,%2,%3};"\
                 : "+f"((c)[0]), "+f"((c)[1]), "+f"((c)[2]), "+f"((c)[3])\
                 : "r"((a)[0]), "r"((a)[1]), "r"((a)[2]), "r"((a)[3]),  \
                   "r"(b0), "r"(b1))

// ---------------------------------------------------------------------------
// HMMA GEMM: C[m, n] = bias[n] + sum_k A[m,k] * (Whi+Wmid+Wlo)[n,k]
// CTA tile 128x128, 8 warps (2 along m x 4 along n), warp tile 64x32.
// BK=32, double-buffered cp.async stages (A + 3 W-split tiles).
// smem rows padded: stride 40 bf16 = 80 B (conflict-free ldmatrix).
// ---------------------------------------------------------------------------
#define BK        32
#define SROW      40            // bf16 elems per padded smem row
#define SROW_B    80            // bytes
#define A_TILE_B  (128 * SROW_B)            // 10240
#define W_TILE_B  (128 * SROW_B)            // per split
#define STAGE_B   (A_TILE_B + 3 * W_TILE_B) // 40960
#define SM_BIAS   0                          // 512 B
#define SM_STAGE  512
#define SM_TOTAL  (SM_STAGE + 2 * STAGE_B)   // 82432

template<int K>
__global__ __launch_bounds__(256)
void hmma_gemm_kernel(const __nv_bfloat16* __restrict__ A,
                      const __nv_bfloat16* __restrict__ Whi,
                      const __nv_bfloat16* __restrict__ Wmid,
                      const __nv_bfloat16* __restrict__ Wlo,
                      const float* __restrict__ bias,
                      float* __restrict__ C, int N) {
    constexpr int CHUNKS = K / BK;
    extern __shared__ char smem[];
    const uint32_t sb = smem_u32(smem);
    const int tid  = threadIdx.x;
    const int wid  = tid >> 5;
    const int lane = tid & 31;
    const int warp_m = wid & 1;       // 0..1
    const int warp_n = wid >> 1;      // 0..3
    const int m0 = blockIdx.y * 128;
    const int n0 = blockIdx.x * 128;

    if (tid < 128) ((float*)(smem + SM_BIAS))[tid] = bias[n0 + tid];

    const __nv_bfloat16* Wp[3] = {Whi, Wmid, Wlo};

    // ---- cp.async prefetch of one chunk into stage buf ----
    auto prefetch = [&](int c, int buf) {
        uint32_t st = sb + SM_STAGE + buf * STAGE_B;
        // A tile: 128 rows x 32 cols bf16 = 512 x 16B
#pragma unroll
        for (int i = 0; i < 2; ++i) {
            int u = tid + i * 256;
            int row = u >> 2, col16 = u & 3;
            const char* g = (const char*)(A + (size_t)(m0 + row) * K + c * BK + col16 * 8);
            CP_ASYNC16(st + row * SROW_B + col16 * 16, g);
        }
#pragma unroll
        for (int s = 0; s < 3; ++s) {
            uint32_t wst = st + A_TILE_B + s * W_TILE_B;
#pragma unroll
            for (int i = 0; i < 2; ++i) {
                int u = tid + i * 256;
                int row = u >> 2, col16 = u & 3;
                const char* g = (const char*)(Wp[s] + (size_t)(n0 + row) * K + c * BK + col16 * 8);
                CP_ASYNC16(wst + row * SROW_B + col16 * 16, g);
            }
        }
        CP_COMMIT();
    };

    float acc[4][4][4];
#pragma unroll
    for (int mi = 0; mi < 4; ++mi)
#pragma unroll
        for (int ni = 0; ni < 4; ++ni)
#pragma unroll
            for (int j = 0; j < 4; ++j) acc[mi][ni][j] = 0.f;

    // ldmatrix lane addressing (within tile)
    const int a_row = warp_m * 64 + (lane & 7) + ((lane >> 3) & 1) * 8;
    const int a_col = (lane >> 4) * 8;                  // k offset
    const int lb    = lane & 15;
    const int b_row = warp_n * 32 + (lb & 7);
    const int b_col = ((lb >> 3) & 1) * 8;

    prefetch(0, 0);

    for (int c = 0; c < CHUNKS; ++c) {
        int buf = c & 1;
        if (c + 1 < CHUNKS) { prefetch(c + 1, buf ^ 1); CP_WAIT(1); }
        else                { CP_WAIT(0); }
        __syncthreads();

        uint32_t a_base = sb + SM_STAGE + buf * STAGE_B;
        uint32_t w_base = a_base + A_TILE_B;

#pragma unroll
        for (int ks = 0; ks < 2; ++ks) {                // two k16 steps per chunk
            uint32_t a_frag[4][4];
#pragma unroll
            for (int mi = 0; mi < 4; ++mi) {
                uint32_t ad = a_base + (uint32_t)(a_row + mi * 16) * SROW_B
                            + (uint32_t)(ks * 16 + a_col) * 2;
                LDSM_X4(a_frag[mi][0], a_frag[mi][1], a_frag[mi][2], a_frag[mi][3], ad);
            }
#pragma unroll
            for (int s = 0; s < 3; ++s) {
#pragma unroll
                for (int ni = 0; ni < 4; ++ni) {
                    uint32_t bd = w_base + s * W_TILE_B
                                + (uint32_t)(b_row + ni * 8) * SROW_B
                                + (uint32_t)(ks * 16 + b_col) * 2;
                    uint32_t b0, b1;
                    LDSM_X2(b0, b1, bd);
#pragma unroll
                    for (int mi = 0; mi < 4; ++mi)
                        MMA_BF16(acc[mi][ni], a_frag[mi], b0, b1);
                }
            }
        }
        __syncthreads();   // stage consumed; safe to overwrite with chunk c+2
    }

    // ---- epilogue: acc + bias -> C (float2 stores) ----
    const float* bias_s = (const float*)(smem + SM_BIAS);
#pragma unroll
    for (int mi = 0; mi < 4; ++mi) {
#pragma unroll
        for (int ni = 0; ni < 4; ++ni) {
            int row = m0 + warp_m * 64 + mi * 16 + (lane >> 2);
            int coll = warp_n * 32 + ni * 8 + (lane & 3) * 2;   // within tile
            int col = n0 + coll;
            float2 v0 = {acc[mi][ni][0] + bias_s[coll],
                         acc[mi][ni][1] + bias_s[coll + 1]};
            float2 v1 = {acc[mi][ni][2] + bias_s[coll],
                         acc[mi][ni][3] + bias_s[coll + 1]};
            *(float2*)(C + (size_t)row * N + col) = v0;
            *(float2*)(C + (size_t)(row + 8) * N + col) = v1;
        }
    }
}

// ---------------------------------------------------------------------------
// Weight 3-way bf16 split (exact: hi+mid+lo == w in fp32)
// ---------------------------------------------------------------------------
__global__ void split_kernel(const float* __restrict__ W,
                             __nv_bfloat16* __restrict__ hi,
                             __nv_bfloat16* __restrict__ mid,
                             __nv_bfloat16* __restrict__ lo, int n) {
    int i = blockIdx.x * blockDim.x + threadIdx.x;
    if (i >= n) return;
    float w = W[i];
    __nv_bfloat16 h = __float2bfloat16(w);
    float r1 = w - __bfloat162float(h);
    __nv_bfloat16 m = __float2bfloat16(r1);
    float r2 = r1 - __bfloat162float(m);
    __nv_bfloat16 l = __float2bfloat16(r2);
    hi[i] = h; mid[i] = m; lo[i] = l;
}

// ---------------------------------------------------------------------------
// Latency encode + mean over S -> bf16 (values k/64, exact)
// ---------------------------------------------------------------------------
__global__ void encode_kernel(const float* __restrict__ x, __nv_bfloat16* __restrict__ out) {
    int b = blockIdx.x;
    int f = threadIdx.x;
    __shared__ float cnt[T_STEPS * F_IN];
#pragma unroll
    for (int t = 0; t < T_STEPS; ++t) cnt[t * F_IN + f] = 0.f;

    const float* xb = x + (size_t)b * S_SZ * F_IN + f;
    float vmin = FLT_MAX, vmax = -FLT_MAX;
#pragma unroll 8
    for (int s = 0; s < S_SZ; ++s) {
        float v = xb[s * F_IN];
        v = (v < 0.75f) ? 0.f : v;
        vmin = fminf(vmin, v);
        vmax = fmaxf(vmax, v);
    }
    float denom = vmax - vmin + 1e-8f;
    const float c1 = 0.0100001f;
    const float tmax = 11.512935464920229f;
#pragma unroll 4
    for (int s = 0; s < S_SZ; ++s) {
        float v = xb[s * F_IN];
        v = (v < 0.75f) ? 0.f : v;
        float xn = (v - vmin) / denom;
        float d = fmaxf(xn, c1);
        float tt = logf(d / (d - 0.01f)) * 31.0f / tmax;
        float r = rintf(tt);
        r = fminf(fmaxf(r, 0.f), 31.f);
        cnt[(int)r * F_IN + f] += 1.0f;
    }
#pragma unroll
    for (int t = 0; t < T_STEPS; ++t)
        out[(size_t)t * (B_SZ * F_IN) + (size_t)b * F_IN + f] =
            __float2bfloat16(cnt[t * F_IN + f] * 0.015625f);
}

// ---------------------------------------------------------------------------
// LIF scan, templated output (bf16 spikes for next layer / fp32 final)
// ---------------------------------------------------------------------------
template<typename OutT>
__global__ void lif_scan_kernel(const float* __restrict__ cur, OutT* __restrict__ spk, int n) {
    int i = blockIdx.x * blockDim.x + threadIdx.x;
    if (i >= n) return;
    float mem = 0.f;
#pragma unroll
    for (int t = 0; t < T_STEPS; ++t) {
        float c = cur[(size_t)t * n + i];
        float reset = (mem > 1.0f) ? 1.0f : 0.0f;
        mem = 0.9f * mem + c - reset;
        spk[(size_t)t * n + i] = (OutT)((mem > 1.0f) ? 1.0f : 0.0f);
    }
}

// ---------------------------------------------------------------------------
extern "C" void kernel_launch(void* const* d_in, const int* in_sizes, int n_in,
                              void* d_out, int out_size) {
    const float* x  = (const float*)d_in[0];
    const float* W1 = (const float*)d_in[1];
    const float* b1 = (const float*)d_in[2];
    const float* W2 = (const float*)d_in[3];
    const float* b2 = (const float*)d_in[4];
    const float* W3 = (const float*)d_in[5];
    const float* b3 = (const float*)d_in[6];
    float* out = (float*)d_out;

    __nv_bfloat16 *spk0, *spk1, *spk2, *ws;
    float* cur;
    cudaGetSymbolAddress((void**)&spk0, g_spk0);
    cudaGetSymbolAddress((void**)&spk1, g_spk1);
    cudaGetSymbolAddress((void**)&spk2, g_spk2);
    cudaGetSymbolAddress((void**)&cur,  g_cur);
    cudaGetSymbolAddress((void**)&ws,   g_wsplit);
    const size_t WS = (size_t)H1 * H1;   // 65536 elements per split slot

    cudaFuncSetAttribute(hmma_gemm_kernel<128>, cudaFuncAttributeMaxDynamicSharedMemorySize, SM_TOTAL);
    cudaFuncSetAttribute(hmma_gemm_kernel<256>, cudaFuncAttributeMaxDynamicSharedMemorySize, SM_TOTAL);

    // weight splits
    split_kernel<<<(H1 * F_IN + 255) / 256, 256>>>(W1, ws + 0 * WS, ws + 1 * WS, ws + 2 * WS, H1 * F_IN);
    split_kernel<<<(H2 * H1 + 255) / 256, 256>>>(W2, ws + 3 * WS, ws + 4 * WS, ws + 5 * WS, H2 * H1);
    split_kernel<<<(H3 * H2 + 255) / 256, 256>>>(W3, ws + 6 * WS, ws + 7 * WS, ws + 8 * WS, H3 * H2);

    // encode
    encode_kernel<<<B_SZ, F_IN>>>(x, spk0);

    // layer 1: (16384 x 128) @ (256 x 128)^T
    hmma_gemm_kernel<128><<<dim3(H1 / 128, M_ROWS / 128), 256, SM_TOTAL>>>(
        spk0, ws + 0 * WS, ws + 1 * WS, ws + 2 * WS, b1, cur, H1);
    lif_scan_kernel<__nv_bfloat16><<<(B_SZ * H1 + 255) / 256, 256>>>(cur, spk1, B_SZ * H1);

    // layer 2: (16384 x 256) @ (256 x 256)^T
    hmma_gemm_kernel<256><<<dim3(H2 / 128, M_ROWS / 128), 256, SM_TOTAL>>>(
        spk1, ws + 3 * WS, ws + 4 * WS, ws + 5 * WS, b2, cur, H2);
    lif_scan_kernel<__nv_bfloat16><<<(B_SZ * H2 + 255) / 256, 256>>>(cur, spk2, B_SZ * H2);

    // layer 3: (16384 x 256) @ (128 x 256)^T -> fp32 out
    hmma_gemm_kernel<256><<<dim3(H3 / 128, M_ROWS / 128), 256, SM_TOTAL>>>(
        spk2, ws + 6 * WS, ws + 7 * WS, ws + 8 * WS, b3, cur, H3);
    lif_scan_kernel<float><<<(B_SZ * H3 + 255) / 256, 256>>>(cur, out, B_SZ * H3);
}

// round 5
// speedup vs baseline: 2.2436x; 1.1381x over previous
#include <cuda_runtime.h>
#include <cuda_bf16.h>
#include <math.h>
#include <float.h>
#include <stdint.h>

#define T_STEPS 32
#define B_SZ    512
#define S_SZ    64
#define F_IN    128
#define H1      256
#define H2      256
#define H3      128
#define M_ROWS  (T_STEPS * B_SZ)   // 16384

// ---------------------------------------------------------------------------
// Scratch (__device__ globals; no allocation allowed)
// ---------------------------------------------------------------------------
__device__ __nv_bfloat16 g_spk0[M_ROWS * F_IN];
__device__ __nv_bfloat16 g_spk1[M_ROWS * H1];
__device__ __nv_bfloat16 g_spk2[M_ROWS * H2];
__device__ float         g_cur [M_ROWS * H1];
__device__ __nv_bfloat16 g_wsplit[9][H1 * H1];   // [layer*3+split][N*K]

// ---------------------------------------------------------------------------
// PTX helpers (baseline sm_80+ features only; no tcgen05)
// ---------------------------------------------------------------------------
__device__ __forceinline__ uint32_t smem_u32(const void* p) {
    uint32_t a;
    asm("{ .reg .u64 t; cvta.to.shared.u64 t, %1; cvt.u32.u64 %0, t; }" : "=r"(a) : "l"(p));
    return a;
}
#define CP_ASYNC16(dst, src) \
    asm volatile("cp.async.cg.shared.global [%0], [%1], 16;" :: "r"(dst), "l"(src))
#define CP_COMMIT() asm volatile("cp.async.commit_group;")
#define CP_WAIT(N)  asm volatile("cp.async.wait_group %0;" :: "n"(N))

#define LDSM_X4(r0, r1, r2, r3, addr)                                   \
    asm volatile("ldmatrix.sync.aligned.m8n8.x4.shared.b16 "            \
                 "{%0,%1,%2,%3}, [%4];"                                 \
                 : "=r"(r0), "=r"(r1), "=r"(r2), "=r"(r3) : "r"(addr))
#define LDSM_X2(r0, r1, addr)                                           \
    asm volatile("ldmatrix.sync.aligned.m8n8.x2.shared.b16 "            \
                 "{%0,%1}, [%2];" : "=r"(r0), "=r"(r1) : "r"(addr))

#define MMA_BF16(c, a, b0, b1)                                          \
    asm volatile("mma.sync.aligned.m16n8k16.row.col.f32.bf16.bf16.f32 " \
                 "{%0,%1,%2,%3}, {%4,%5,%6,%7}, {%8,%9}, {%0,%1,%2,%3};"\
                 : "+f"((c)[0]), "+f"((c)[1]), "+f"((c)[2]), "+f"((c)[3])\
                 : "r"((a)[0]), "r"((a)[1]), "r"((a)[2]), "r"((a)[3]),  \
                   "r"(b0), "r"(b1))

// ---------------------------------------------------------------------------
// HMMA GEMM: C[m, n] = bias[n] + sum_k A[m,k] * (Whi+Wmid+Wlo)[n,k]
// CTA tile 128x128, 8 warps (2 along m x 4 along n), warp tile 64x32.
// BK=32, double-buffered cp.async stages (A + 3 W-split tiles).
// smem rows padded: stride 40 bf16 = 80 B (conflict-free ldmatrix).
// ---------------------------------------------------------------------------
#define BK        32
#define SROW      40
#define SROW_B    80
#define A_TILE_B  (128 * SROW_B)
#define W_TILE_B  (128 * SROW_B)
#define STAGE_B   (A_TILE_B + 3 * W_TILE_B)
#define SM_BIAS   0
#define SM_STAGE  512
#define SM_TOTAL  (SM_STAGE + 2 * STAGE_B)   // 82432

template<int K>
__global__ __launch_bounds__(256)
void hmma_gemm_kernel(const __nv_bfloat16* __restrict__ A,
                      const __nv_bfloat16* __restrict__ Whi,
                      const __nv_bfloat16* __restrict__ Wmid,
                      const __nv_bfloat16* __restrict__ Wlo,
                      const float* __restrict__ bias,
                      float* __restrict__ C, int N) {
    constexpr int CHUNKS = K / BK;
    extern __shared__ char smem[];
    const uint32_t sb = smem_u32(smem);
    const int tid  = threadIdx.x;
    const int wid  = tid >> 5;
    const int lane = tid & 31;
    const int warp_m = wid & 1;
    const int warp_n = wid >> 1;
    const int m0 = blockIdx.y * 128;
    const int n0 = blockIdx.x * 128;

    if (tid < 128) ((float*)(smem + SM_BIAS))[tid] = bias[n0 + tid];

    const __nv_bfloat16* Wp[3] = {Whi, Wmid, Wlo};

    auto prefetch = [&](int c, int buf) {
        uint32_t st = sb + SM_STAGE + buf * STAGE_B;
#pragma unroll
        for (int i = 0; i < 2; ++i) {
            int u = tid + i * 256;
            int row = u >> 2, col16 = u & 3;
            const char* g = (const char*)(A + (size_t)(m0 + row) * K + c * BK + col16 * 8);
            CP_ASYNC16(st + row * SROW_B + col16 * 16, g);
        }
#pragma unroll
        for (int s = 0; s < 3; ++s) {
            uint32_t wst = st + A_TILE_B + s * W_TILE_B;
#pragma unroll
            for (int i = 0; i < 2; ++i) {
                int u = tid + i * 256;
                int row = u >> 2, col16 = u & 3;
                const char* g = (const char*)(Wp[s] + (size_t)(n0 + row) * K + c * BK + col16 * 8);
                CP_ASYNC16(wst + row * SROW_B + col16 * 16, g);
            }
        }
        CP_COMMIT();
    };

    float acc[4][4][4];
#pragma unroll
    for (int mi = 0; mi < 4; ++mi)
#pragma unroll
        for (int ni = 0; ni < 4; ++ni)
#pragma unroll
            for (int j = 0; j < 4; ++j) acc[mi][ni][j] = 0.f;

    const int a_row = warp_m * 64 + (lane & 7) + ((lane >> 3) & 1) * 8;
    const int a_col = (lane >> 4) * 8;
    const int lb    = lane & 15;
    const int b_row = warp_n * 32 + (lb & 7);
    const int b_col = ((lb >> 3) & 1) * 8;

    prefetch(0, 0);

    for (int c = 0; c < CHUNKS; ++c) {
        int buf = c & 1;
        if (c + 1 < CHUNKS) { prefetch(c + 1, buf ^ 1); CP_WAIT(1); }
        else                { CP_WAIT(0); }
        __syncthreads();

        uint32_t a_base = sb + SM_STAGE + buf * STAGE_B;
        uint32_t w_base = a_base + A_TILE_B;

#pragma unroll
        for (int ks = 0; ks < 2; ++ks) {
            uint32_t a_frag[4][4];
#pragma unroll
            for (int mi = 0; mi < 4; ++mi) {
                uint32_t ad = a_base + (uint32_t)(a_row + mi * 16) * SROW_B
                            + (uint32_t)(ks * 16 + a_col) * 2;
                LDSM_X4(a_frag[mi][0], a_frag[mi][1], a_frag[mi][2], a_frag[mi][3], ad);
            }
#pragma unroll
            for (int s = 0; s < 3; ++s) {
#pragma unroll
                for (int ni = 0; ni < 4; ++ni) {
                    uint32_t bd = w_base + s * W_TILE_B
                                + (uint32_t)(b_row + ni * 8) * SROW_B
                                + (uint32_t)(ks * 16 + b_col) * 2;
                    uint32_t b0, b1;
                    LDSM_X2(b0, b1, bd);
#pragma unroll
                    for (int mi = 0; mi < 4; ++mi)
                        MMA_BF16(acc[mi][ni], a_frag[mi], b0, b1);
                }
            }
        }
        __syncthreads();
    }

    const float* bias_s = (const float*)(smem + SM_BIAS);
#pragma unroll
    for (int mi = 0; mi < 4; ++mi) {
#pragma unroll
        for (int ni = 0; ni < 4; ++ni) {
            int row = m0 + warp_m * 64 + mi * 16 + (lane >> 2);
            int coll = warp_n * 32 + ni * 8 + (lane & 3) * 2;
            int col = n0 + coll;
            float2 v0 = {acc[mi][ni][0] + bias_s[coll],
                         acc[mi][ni][1] + bias_s[coll + 1]};
            float2 v1 = {acc[mi][ni][2] + bias_s[coll],
                         acc[mi][ni][3] + bias_s[coll + 1]};
            *(float2*)(C + (size_t)row * N + col) = v0;
            *(float2*)(C + (size_t)(row + 8) * N + col) = v1;
        }
    }
}

// ---------------------------------------------------------------------------
// Weight 3-way bf16 split (exact: hi+mid+lo == w in fp32)
// ---------------------------------------------------------------------------
__global__ void split_kernel(const float* __restrict__ W,
                             __nv_bfloat16* __restrict__ hi,
                             __nv_bfloat16* __restrict__ mid,
                             __nv_bfloat16* __restrict__ lo, int n) {
    int i = blockIdx.x * blockDim.x + threadIdx.x;
    if (i >= n) return;
    float w = W[i];
    __nv_bfloat16 h = __float2bfloat16(w);
    float r1 = w - __bfloat162float(h);
    __nv_bfloat16 m = __float2bfloat16(r1);
    float r2 = r1 - __bfloat162float(m);
    __nv_bfloat16 l = __float2bfloat16(r2);
    hi[i] = h; mid[i] = m; lo[i] = l;
}

// ---------------------------------------------------------------------------
// Latency encode + mean over S -> bf16.
// Block = batch b, 512 threads = 4 s-groups x 128 features.
// Each thread: 16 gated values in regs, min/max reduced via shared,
// 16 spike times -> int histogram (atomicAdd, exact/deterministic).
// ---------------------------------------------------------------------------
__global__ __launch_bounds__(512)
void encode_kernel(const float* __restrict__ x, __nv_bfloat16* __restrict__ out) {
    int b   = blockIdx.x;
    int tid = threadIdx.x;
    int f   = tid & 127;
    int sg  = tid >> 7;                    // s-group 0..3

    __shared__ float red[8][F_IN];         // [0..3] mins, [4..7] maxs
    __shared__ int   cnt[T_STEPS * F_IN];  // 16 KB

#pragma unroll
    for (int i = 0; i < 8; ++i) cnt[tid + i * 512] = 0;

    const float* xb = x + (size_t)b * S_SZ * F_IN + (size_t)sg * 16 * F_IN + f;

    float vals[16];
    float vmin = FLT_MAX, vmax = -FLT_MAX;
#pragma unroll
    for (int i = 0; i < 16; ++i) {
        float v = xb[i * F_IN];
        v = (v < 0.75f) ? 0.f : v;
        vals[i] = v;
        vmin = fminf(vmin, v);
        vmax = fmaxf(vmax, v);
    }
    red[sg][f]     = vmin;
    red[4 + sg][f] = vmax;
    __syncthreads();

    float gmin = fminf(fminf(red[0][f], red[1][f]), fminf(red[2][f], red[3][f]));
    float gmax = fmaxf(fmaxf(red[4][f], red[5][f]), fmaxf(red[6][f], red[7][f]));
    float denom = gmax - gmin + 1e-8f;

    const float c1   = 0.0100001f;            // float(LAT_THR + EPS)
    const float tmax = 11.512935464920229f;   // log((0.01+1e-7)/1e-7)

#pragma unroll
    for (int i = 0; i < 16; ++i) {
        float xn = (vals[i] - gmin) / denom;
        float d  = fmaxf(xn, c1);
        float tt = logf(d / (d - 0.01f)) * 31.0f / tmax;
        float r  = rintf(tt);
        r = fminf(fmaxf(r, 0.f), 31.f);
        atomicAdd(&cnt[(int)r * F_IN + f], 1);
    }
    __syncthreads();

#pragma unroll
    for (int i = 0; i < 8; ++i) {
        int flat = tid + i * 512;
        int t = flat >> 7, ff = flat & 127;
        out[(size_t)t * (B_SZ * F_IN) + (size_t)b * F_IN + ff] =
            __float2bfloat16((float)cnt[t * F_IN + ff] * 0.015625f);
    }
}

// ---------------------------------------------------------------------------
// LIF scan, templated output (bf16 spikes for next layer / fp32 final)
// ---------------------------------------------------------------------------
template<typename OutT>
__global__ void lif_scan_kernel(const float* __restrict__ cur, OutT* __restrict__ spk, int n) {
    int i = blockIdx.x * blockDim.x + threadIdx.x;
    if (i >= n) return;
    float mem = 0.f;
#pragma unroll
    for (int t = 0; t < T_STEPS; ++t) {
        float c = cur[(size_t)t * n + i];
        float reset = (mem > 1.0f) ? 1.0f : 0.0f;
        mem = 0.9f * mem + c - reset;
        spk[(size_t)t * n + i] = (OutT)((mem > 1.0f) ? 1.0f : 0.0f);
    }
}

// ---------------------------------------------------------------------------
extern "C" void kernel_launch(void* const* d_in, const int* in_sizes, int n_in,
                              void* d_out, int out_size) {
    const float* x  = (const float*)d_in[0];
    const float* W1 = (const float*)d_in[1];
    const float* b1 = (const float*)d_in[2];
    const float* W2 = (const float*)d_in[3];
    const float* b2 = (const float*)d_in[4];
    const float* W3 = (const float*)d_in[5];
    const float* b3 = (const float*)d_in[6];
    float* out = (float*)d_out;

    __nv_bfloat16 *spk0, *spk1, *spk2, *ws;
    float* cur;
    cudaGetSymbolAddress((void**)&spk0, g_spk0);
    cudaGetSymbolAddress((void**)&spk1, g_spk1);
    cudaGetSymbolAddress((void**)&spk2, g_spk2);
    cudaGetSymbolAddress((void**)&cur,  g_cur);
    cudaGetSymbolAddress((void**)&ws,   g_wsplit);
    const size_t WS = (size_t)H1 * H1;

    cudaFuncSetAttribute(hmma_gemm_kernel<128>, cudaFuncAttributeMaxDynamicSharedMemorySize, SM_TOTAL);
    cudaFuncSetAttribute(hmma_gemm_kernel<256>, cudaFuncAttributeMaxDynamicSharedMemorySize, SM_TOTAL);

    // weight splits
    split_kernel<<<(H1 * F_IN + 255) / 256, 256>>>(W1, ws + 0 * WS, ws + 1 * WS, ws + 2 * WS, H1 * F_IN);
    split_kernel<<<(H2 * H1 + 255) / 256, 256>>>(W2, ws + 3 * WS, ws + 4 * WS, ws + 5 * WS, H2 * H1);
    split_kernel<<<(H3 * H2 + 255) / 256, 256>>>(W3, ws + 6 * WS, ws + 7 * WS, ws + 8 * WS, H3 * H2);

    // encode
    encode_kernel<<<B_SZ, 512>>>(x, spk0);

    // layer 1: (16384 x 128) @ (256 x 128)^T
    hmma_gemm_kernel<128><<<dim3(H1 / 128, M_ROWS / 128), 256, SM_TOTAL>>>(
        spk0, ws + 0 * WS, ws + 1 * WS, ws + 2 * WS, b1, cur, H1);
    lif_scan_kernel<__nv_bfloat16><<<(B_SZ * H1 + 255) / 256, 256>>>(cur, spk1, B_SZ * H1);

    // layer 2: (16384 x 256) @ (256 x 256)^T
    hmma_gemm_kernel<256><<<dim3(H2 / 128, M_ROWS / 128), 256, SM_TOTAL>>>(
        spk1, ws + 3 * WS, ws + 4 * WS, ws + 5 * WS, b2, cur, H2);
    lif_scan_kernel<__nv_bfloat16><<<(B_SZ * H2 + 255) / 256, 256>>>(cur, spk2, B_SZ * H2);

    // layer 3: (16384 x 256) @ (128 x 256)^T -> fp32 out
    hmma_gemm_kernel<256><<<dim3(H3 / 128, M_ROWS / 128), 256, SM_TOTAL>>>(
        spk2, ws + 6 * WS, ws + 7 * WS, ws + 8 * WS, b3, cur, H3);
    lif_scan_kernel<float><<<(B_SZ * H3 + 255) / 256, 256>>>(cur, out, B_SZ * H3);
}

// round 6
// speedup vs baseline: 2.7692x; 1.2343x over previous
#include <cuda_runtime.h>
#include <cuda_bf16.h>
#include <math.h>
#include <float.h>
#include <stdint.h>

#define T_STEPS 32
#define B_SZ    512
#define S_SZ    64
#define F_IN    128
#define H1      256
#define H2      256
#define H3      128
#define M_ROWS  (T_STEPS * B_SZ)   // 16384

// ---------------------------------------------------------------------------
// Scratch (__device__ globals; no allocation allowed)
// Row layout for all activation matrices: r = b*32 + t  (b-major)
// ---------------------------------------------------------------------------
__device__ __nv_bfloat16 g_spk0[M_ROWS * F_IN];
__device__ __nv_bfloat16 g_spk1[M_ROWS * H1];
__device__ __nv_bfloat16 g_spk2[M_ROWS * H2];
__device__ __nv_bfloat16 g_wsplit[9][H1 * H1];   // [layer*3+split][N*K]

// ---------------------------------------------------------------------------
// PTX helpers (baseline sm_80+ features only)
// ---------------------------------------------------------------------------
__device__ __forceinline__ uint32_t smem_u32(const void* p) {
    uint32_t a;
    asm("{ .reg .u64 t; cvta.to.shared.u64 t, %1; cvt.u32.u64 %0, t; }" : "=r"(a) : "l"(p));
    return a;
}
#define CP_ASYNC16(dst, src) \
    asm volatile("cp.async.cg.shared.global [%0], [%1], 16;" :: "r"(dst), "l"(src))
#define CP_COMMIT() asm volatile("cp.async.commit_group;")
#define CP_WAIT(N)  asm volatile("cp.async.wait_group %0;" :: "n"(N))

#define LDSM_X4(r0, r1, r2, r3, addr)                                   \
    asm volatile("ldmatrix.sync.aligned.m8n8.x4.shared.b16 "            \
                 "{%0,%1,%2,%3}, [%4];"                                 \
                 : "=r"(r0), "=r"(r1), "=r"(r2), "=r"(r3) : "r"(addr))
#define LDSM_X2(r0, r1, addr)                                           \
    asm volatile("ldmatrix.sync.aligned.m8n8.x2.shared.b16 "            \
                 "{%0,%1}, [%2];" : "=r"(r0), "=r"(r1) : "r"(addr))

#define MMA_BF16(c, a, b0, b1)                                          \
    asm volatile("mma.sync.aligned.m16n8k16.row.col.f32.bf16.bf16.f32 " \
                 "{%0,%1,%2,%3}, {%4,%5,%6,%7}, {%8,%9}, {%0,%1,%2,%3};"\
                 : "+f"((c)[0]), "+f"((c)[1]), "+f"((c)[2]), "+f"((c)[3])\
                 : "r"((a)[0]), "r"((a)[1]), "r"((a)[2]), "r"((a)[3]),  \
                   "r"(b0), "r"(b1))

// ---------------------------------------------------------------------------
// Fused HMMA GEMM + LIF scan.
// C_tile[m, n] = bias[n] + sum_k A[m,k]*(Whi+Wmid+Wlo)[n,k], staged in smem,
// then the 4 batches x 32 timesteps in the 128-row tile are scanned in-place.
// CTA tile 128x128, 8 warps, BK=32, double-buffered cp.async.
// ---------------------------------------------------------------------------
#define BK        32
#define SROW_B    80
#define A_TILE_B  (128 * SROW_B)
#define W_TILE_B  (128 * SROW_B)
#define STAGE_B   (A_TILE_B + 3 * W_TILE_B)
#define SM_BIAS   0
#define SM_STAGE  512
#define SM_TOTAL  (SM_STAGE + 2 * STAGE_B)   // 82432
#define STP       130                        // epilogue stage pitch (floats)

template<int K, bool FINAL>
__global__ __launch_bounds__(256)
void hmma_gemm_lif_kernel(const __nv_bfloat16* __restrict__ A,
                          const __nv_bfloat16* __restrict__ Whi,
                          const __nv_bfloat16* __restrict__ Wmid,
                          const __nv_bfloat16* __restrict__ Wlo,
                          const float* __restrict__ bias,
                          __nv_bfloat16* __restrict__ spk_out,
                          float* __restrict__ final_out,
                          int N) {
    constexpr int CHUNKS = K / BK;
    extern __shared__ char smem[];
    const uint32_t sb = smem_u32(smem);
    const int tid  = threadIdx.x;
    const int wid  = tid >> 5;
    const int lane = tid & 31;
    const int warp_m = wid & 1;
    const int warp_n = wid >> 1;
    const int m0 = blockIdx.y * 128;
    const int n0 = blockIdx.x * 128;

    if (tid < 128) ((float*)(smem + SM_BIAS))[tid] = bias[n0 + tid];

    const __nv_bfloat16* Wp[3] = {Whi, Wmid, Wlo};

    auto prefetch = [&](int c, int buf) {
        uint32_t st = sb + SM_STAGE + buf * STAGE_B;
#pragma unroll
        for (int i = 0; i < 2; ++i) {
            int u = tid + i * 256;
            int row = u >> 2, col16 = u & 3;
            const char* g = (const char*)(A + (size_t)(m0 + row) * K + c * BK + col16 * 8);
            CP_ASYNC16(st + row * SROW_B + col16 * 16, g);
        }
#pragma unroll
        for (int s = 0; s < 3; ++s) {
            uint32_t wst = st + A_TILE_B + s * W_TILE_B;
#pragma unroll
            for (int i = 0; i < 2; ++i) {
                int u = tid + i * 256;
                int row = u >> 2, col16 = u & 3;
                const char* g = (const char*)(Wp[s] + (size_t)(n0 + row) * K + c * BK + col16 * 8);
                CP_ASYNC16(wst + row * SROW_B + col16 * 16, g);
            }
        }
        CP_COMMIT();
    };

    float acc[4][4][4];
#pragma unroll
    for (int mi = 0; mi < 4; ++mi)
#pragma unroll
        for (int ni = 0; ni < 4; ++ni)
#pragma unroll
            for (int j = 0; j < 4; ++j) acc[mi][ni][j] = 0.f;

    const int a_row = warp_m * 64 + (lane & 7) + ((lane >> 3) & 1) * 8;
    const int a_col = (lane >> 4) * 8;
    const int lb16  = lane & 15;
    const int b_row = warp_n * 32 + (lb16 & 7);
    const int b_col = ((lb16 >> 3) & 1) * 8;

    prefetch(0, 0);

    for (int c = 0; c < CHUNKS; ++c) {
        int buf = c & 1;
        if (c + 1 < CHUNKS) { prefetch(c + 1, buf ^ 1); CP_WAIT(1); }
        else                { CP_WAIT(0); }
        __syncthreads();

        uint32_t a_base = sb + SM_STAGE + buf * STAGE_B;
        uint32_t w_base = a_base + A_TILE_B;

#pragma unroll
        for (int ks = 0; ks < 2; ++ks) {
            uint32_t a_frag[4][4];
#pragma unroll
            for (int mi = 0; mi < 4; ++mi) {
                uint32_t ad = a_base + (uint32_t)(a_row + mi * 16) * SROW_B
                            + (uint32_t)(ks * 16 + a_col) * 2;
                LDSM_X4(a_frag[mi][0], a_frag[mi][1], a_frag[mi][2], a_frag[mi][3], ad);
            }
#pragma unroll
            for (int s = 0; s < 3; ++s) {
#pragma unroll
                for (int ni = 0; ni < 4; ++ni) {
                    uint32_t bd = w_base + s * W_TILE_B
                                + (uint32_t)(b_row + ni * 8) * SROW_B
                                + (uint32_t)(ks * 16 + b_col) * 2;
                    uint32_t b0, b1;
                    LDSM_X2(b0, b1, bd);
#pragma unroll
                    for (int mi = 0; mi < 4; ++mi)
                        MMA_BF16(acc[mi][ni], a_frag[mi], b0, b1);
                }
            }
        }
        __syncthreads();   // all smem reads done; buffers reusable (incl. stage)
    }

    // ---- epilogue part 1: acc + bias -> f32 stage in smem ----
    float* stage = (float*)(smem + SM_STAGE);
    const float* bias_s = (const float*)(smem + SM_BIAS);
#pragma unroll
    for (int mi = 0; mi < 4; ++mi) {
#pragma unroll
        for (int ni = 0; ni < 4; ++ni) {
            int row  = warp_m * 64 + mi * 16 + (lane >> 2);
            int coll = warp_n * 32 + ni * 8 + (lane & 3) * 2;
            stage[row * STP + coll]           = acc[mi][ni][0] + bias_s[coll];
            stage[row * STP + coll + 1]       = acc[mi][ni][1] + bias_s[coll + 1];
            stage[(row + 8) * STP + coll]     = acc[mi][ni][2] + bias_s[coll];
            stage[(row + 8) * STP + coll + 1] = acc[mi][ni][3] + bias_s[coll + 1];
        }
    }
    __syncthreads();

    // ---- epilogue part 2: LIF scan over the 32 timesteps of each batch ----
    // tile rows = 4 batches (lb) x 32 timesteps. 512 scan lanes, 2 per thread.
    {
        int n  = tid & 63;            // columns n and n+64
        int lb = tid >> 6;            // local batch 0..3
        float mem0 = 0.f, mem1 = 0.f;
#pragma unroll
        for (int t = 0; t < T_STEPS; ++t) {
            const float* rowp = stage + (lb * 32 + t) * STP;
            float c0 = rowp[n];
            float c1 = rowp[n + 64];
            float r0 = (mem0 > 1.0f) ? 1.0f : 0.0f;
            float r1 = (mem1 > 1.0f) ? 1.0f : 0.0f;
            mem0 = 0.9f * mem0 + c0 - r0;
            mem1 = 0.9f * mem1 + c1 - r1;
            float s0 = (mem0 > 1.0f) ? 1.0f : 0.0f;
            float s1 = (mem1 > 1.0f) ? 1.0f : 0.0f;
            if (FINAL) {
                // final output is (T, B, N) t-major
                size_t base = (size_t)t * (B_SZ * N) + (size_t)(m0 / 32 + lb) * N + n0;
                final_out[base + n]      = s0;
                final_out[base + n + 64] = s1;
            } else {
                size_t base = (size_t)(m0 + lb * 32 + t) * N + n0;
                spk_out[base + n]      = __float2bfloat16(s0);
                spk_out[base + n + 64] = __float2bfloat16(s1);
            }
        }
    }
}

// ---------------------------------------------------------------------------
// All three weight 3-way bf16 splits in one launch (exact Dekker split)
// ---------------------------------------------------------------------------
__global__ void split_all_kernel(const float* __restrict__ W1,
                                 const float* __restrict__ W2,
                                 const float* __restrict__ W3,
                                 __nv_bfloat16* __restrict__ ws) {
    const size_t WS = (size_t)H1 * H1;     // 65536 per slot
    int i = blockIdx.x * blockDim.x + threadIdx.x;   // 0..131071
    float w; int slot, off;
    if (i < 32768)       { w = W1[i];          slot = 0; off = i; }
    else if (i < 98304)  { w = W2[i - 32768];  slot = 3; off = i - 32768; }
    else                 { w = W3[i - 98304];  slot = 6; off = i - 98304; }
    __nv_bfloat16 h = __float2bfloat16(w);
    float r1 = w - __bfloat162float(h);
    __nv_bfloat16 m = __float2bfloat16(r1);
    float r2 = r1 - __bfloat162float(m);
    __nv_bfloat16 l = __float2bfloat16(r2);
    ws[slot * WS + off]       = h;
    ws[(slot + 1) * WS + off] = m;
    ws[(slot + 2) * WS + off] = l;
}

// ---------------------------------------------------------------------------
// Latency encode + mean over S -> bf16, b-major rows (r = b*32 + t).
// Fast-path binning:
//   d == c1 (zeros / clipped)      -> constant bin, computed once via the
//                                     identical logf chain (bit-identical).
//   d > 0.07 (all thresholds<0.06) -> bin 0 (t(0.07)=0.415, margin >> f32 err)
//   else                            -> exact logf chain fallback (rare).
// ---------------------------------------------------------------------------
__global__ __launch_bounds__(512)
void encode_kernel(const float* __restrict__ x, __nv_bfloat16* __restrict__ out) {
    int b   = blockIdx.x;
    int tid = threadIdx.x;
    int f   = tid & 127;
    int sg  = tid >> 7;                    // s-group 0..3

    __shared__ float red[8][F_IN];
    __shared__ int   cnt[T_STEPS * F_IN];

#pragma unroll
    for (int i = 0; i < 8; ++i) cnt[tid + i * 512] = 0;

    const float* xb = x + (size_t)b * S_SZ * F_IN + (size_t)sg * 16 * F_IN + f;

    float vals[16];
    float vmin = FLT_MAX, vmax = -FLT_MAX;
#pragma unroll
    for (int i = 0; i < 16; ++i) {
        float v = xb[i * F_IN];
        v = (v < 0.75f) ? 0.f : v;
        vals[i] = v;
        vmin = fminf(vmin, v);
        vmax = fmaxf(vmax, v);
    }
    red[sg][f]     = vmin;
    red[4 + sg][f] = vmax;
    __syncthreads();

    float gmin = fminf(fminf(red[0][f], red[1][f]), fminf(red[2][f], red[3][f]));
    float gmax = fmaxf(fmaxf(red[4][f], red[5][f]), fmaxf(red[6][f], red[7][f]));
    float denom = gmax - gmin + 1e-8f;

    const float c1   = 0.0100001f;            // float(LAT_THR + EPS)
    const float tmax = 11.512935464920229f;   // log((0.01+1e-7)/1e-7)

    // constant bin for d == c1 (same chain as reference, evaluated once)
    int idx_c1;
    {
        float tt = logf(c1 / (c1 - 0.01f)) * 31.0f / tmax;
        float r  = rintf(tt);
        idx_c1 = (int)fminf(fmaxf(r, 0.f), 31.f);
    }

#pragma unroll
    for (int i = 0; i < 16; ++i) {
        float xn = (vals[i] - gmin) / denom;
        float d  = fmaxf(xn, c1);
        int idx;
        if (d == c1) {
            idx = idx_c1;
        } else if (d > 0.07f) {
            idx = 0;
        } else {
            float tt = logf(d / (d - 0.01f)) * 31.0f / tmax;
            float r  = rintf(tt);
            idx = (int)fminf(fmaxf(r, 0.f), 31.f);
        }
        atomicAdd(&cnt[idx * F_IN + f], 1);
    }
    __syncthreads();

#pragma unroll
    for (int i = 0; i < 8; ++i) {
        int flat = tid + i * 512;
        int t = flat >> 7, ff = flat & 127;
        out[((size_t)b * T_STEPS + t) * F_IN + ff] =
            __float2bfloat16((float)cnt[t * F_IN + ff] * 0.015625f);
    }
}

// ---------------------------------------------------------------------------
extern "C" void kernel_launch(void* const* d_in, const int* in_sizes, int n_in,
                              void* d_out, int out_size) {
    const float* x  = (const float*)d_in[0];
    const float* W1 = (const float*)d_in[1];
    const float* b1 = (const float*)d_in[2];
    const float* W2 = (const float*)d_in[3];
    const float* b2 = (const float*)d_in[4];
    const float* W3 = (const float*)d_in[5];
    const float* b3 = (const float*)d_in[6];
    float* out = (float*)d_out;

    __nv_bfloat16 *spk0, *spk1, *spk2, *ws;
    cudaGetSymbolAddress((void**)&spk0, g_spk0);
    cudaGetSymbolAddress((void**)&spk1, g_spk1);
    cudaGetSymbolAddress((void**)&spk2, g_spk2);
    cudaGetSymbolAddress((void**)&ws,   g_wsplit);
    const size_t WS = (size_t)H1 * H1;

    cudaFuncSetAttribute(hmma_gemm_lif_kernel<128, false>, cudaFuncAttributeMaxDynamicSharedMemorySize, SM_TOTAL);
    cudaFuncSetAttribute(hmma_gemm_lif_kernel<256, false>, cudaFuncAttributeMaxDynamicSharedMemorySize, SM_TOTAL);
    cudaFuncSetAttribute(hmma_gemm_lif_kernel<256, true>,  cudaFuncAttributeMaxDynamicSharedMemorySize, SM_TOTAL);

    // weight splits (one launch) + encode
    split_all_kernel<<<512, 256>>>(W1, W2, W3, ws);
    encode_kernel<<<B_SZ, 512>>>(x, spk0);

    // layer 1: (16384 x 128) @ (256 x 128)^T, fused LIF
    hmma_gemm_lif_kernel<128, false><<<dim3(H1 / 128, M_ROWS / 128), 256, SM_TOTAL>>>(
        spk0, ws + 0 * WS, ws + 1 * WS, ws + 2 * WS, b1, spk1, nullptr, H1);

    // layer 2: (16384 x 256) @ (256 x 256)^T, fused LIF
    hmma_gemm_lif_kernel<256, false><<<dim3(H2 / 128, M_ROWS / 128), 256, SM_TOTAL>>>(
        spk1, ws + 3 * WS, ws + 4 * WS, ws + 5 * WS, b2, spk2, nullptr, H2);

    // layer 3: (16384 x 256) @ (128 x 256)^T, fused LIF -> (T,B,H3) f32 out
    hmma_gemm_lif_kernel<256, true><<<dim3(H3 / 128, M_ROWS / 128), 256, SM_TOTAL>>>(
        spk2, ws + 6 * WS, ws + 7 * WS, ws + 8 * WS, b3, nullptr, out, H3);
}